// round 14
// baseline (speedup 1.0000x reference)
#include <cuda_runtime.h>
#include <cuda_bf16.h>
#include <cstdint>

#define NN   882
#define TN   1764
#define MOCC 1024
#define BB   8
#define TT   6
#define KK   24
#define MAXD 32
#define CMAXD 24
#define PADCD 16
#define NW   56                      // ceil(1764/32)
#define DUMMY_EDGE (MOCC * MAXD)     // points at always-zero padding row of d_C

#define HW_WORDS  (MOCC * NW)        // 57344
#define WW_WORDS  (TT * MOCC * NW)   // 344064
#define SCAN_WORDS (HW_WORDS + WW_WORDS)             // 401408 = 1568*256
#define GATH_BLOCKS (TT * MOCC * MAXD / 256)         // 768
#define SORT_BLOCKS ((TN + 255) / 256)               // 7

// cluster kernel geometry: 8 clusters (1/batch) x 16 CTAs x 1024 threads
#define CLSZ   16
#define BPTHR  1024
#define NCW    (CLSZ * (BPTHR / 32))  // 512 warps per cluster
#define CNP    (MOCC / 2)             // 512 packed CN tasks = exactly 1 per warp
#define LT2    (2 * KK)               // 48 per-batch loss-term tasks

// ---------------- device scratch (no allocations allowed) ----------------
__device__ unsigned d_hmask[MOCC][NW];        // H nonzero bitmasks
__device__ int   d_row_deg[MOCC];
__device__ int   d_row_cols[MOCC][MAXD];
__device__ int   d_col_cnt[TN];               // atomic counters (self-resetting)
__device__ int   d_col_deg[TN];
__device__ int   d_col_edges[TN][CMAXD];      // edge idx = m*MAXD + slot (sorted, padded)
__device__ float d_C[BB][MOCC + 1][MAXD];     // c2v messages; row MOCC = permanent zeros
__device__ float d_wedge[TT][MOCC][MAXD];     // pre-gathered w_vn on edges
__device__ float d_Gamma[BB][TN];
__device__ float d_pm2[2][BB][TN];            // double-buffered masked prob
__device__ float d_synsign[BB][MOCC];         // (1 - 2*syn)
__device__ float d_lossterm2[BB][TT][LT2];
__device__ float d_lossb[BB];                 // per-batch final scalar
__device__ int   g_done;                      // cross-cluster finish counter
__device__ unsigned d_wneg[TT][MOCC][NW];     // sign bitmasks of w_vn[0..5]
__device__ unsigned d_wnz [TT][MOCC][NW];
__device__ unsigned d_gneg[BB][NW];           // sign bitmasks of Gamma
__device__ unsigned d_gnz [BB][NW];

// cluster barrier: arrive = .release, wait = .acquire (cluster scope)
__device__ __forceinline__ void cbar() {
    asm volatile("barrier.cluster.arrive.aligned;" ::: "memory");
    asm volatile("barrier.cluster.wait.aligned;" ::: "memory");
}

// ---------------- accurate fp32 math (flag-independent; rn division) ----
__device__ __forceinline__ float acc_expf(float x) {
    if (x < -87.0f) return 0.0f;
    if (x >  88.0f) return __int_as_float(0x7f800000);
    float kf = rintf(x * 1.4426950408889634f);
    float r  = fmaf(-kf, 0.693359375f, x);
    r = fmaf(kf, 2.12194440e-4f, r);
    float p = 1.9841270e-4f;
    p = fmaf(r, p, 1.3888889e-3f);
    p = fmaf(r, p, 8.3333333e-3f);
    p = fmaf(r, p, 4.1666667e-2f);
    p = fmaf(r, p, 1.6666667e-1f);
    p = fmaf(r, p, 0.5f);
    p = fmaf(r, p, 1.0f);
    p = fmaf(r, p, 1.0f);
    int k = (int)kf;
    float sc = __int_as_float((k + 127) << 23);
    return p * sc;
}

// log for t>0; returns EXACT +-0.0f at t==1.0f (load-bearing for phi semantics)
__device__ __forceinline__ float acc_logf(float t) {
    int ix = __float_as_int(t);
    int e  = ((ix >> 23) & 0xff) - 127;
    float m = __int_as_float((ix & 0x007fffff) | 0x3f800000);   // [1,2)
    if (m > 1.4142135f) { m *= 0.5f; e += 1; }
    float f  = m - 1.0f;
    float s  = __fdiv_rn(f, 2.0f + f);
    float s2 = s * s;
    float p  = fmaf(s2, 0.11111111f, 0.14285714f);
    p = fmaf(s2, p, 0.2f);
    p = fmaf(s2, p, 0.33333333f);
    float lm = fmaf(2.0f * s, s2 * p, 2.0f * s);
    float r  = fmaf((float)e, 0.693359375f, lm);
    r = fmaf((float)e, -2.12194440e-4f, r);
    return r;
}

// XLA / Eigen fast-tanh (f32, FMA variant) — bit-matches jnp.tanh on GPU.
__device__ __forceinline__ float xla_tanhf(float x) {
    float ax = fabsf(x);
    float xc = fminf(fmaxf(x, -7.99881172180175781f), 7.99881172180175781f);
    float x2 = xc * xc;
    float p = -2.76076847742355e-16f;
    p = fmaf(x2, p,  2.00018790482477e-13f);
    p = fmaf(x2, p, -8.60467152213735e-11f);
    p = fmaf(x2, p,  5.12229709037114e-08f);
    p = fmaf(x2, p,  1.48572235717979e-05f);
    p = fmaf(x2, p,  6.37261928875436e-04f);
    p = fmaf(x2, p,  4.89352455891786e-03f);
    float num = xc * p;
    float q = 1.19825839466702e-06f;
    q = fmaf(x2, q, 1.18534705686654e-04f);
    q = fmaf(x2, q, 2.26843463243900e-03f);
    q = fmaf(x2, q, 4.89352518554385e-03f);
    float r = __fdiv_rn(num, q);
    return (ax < 0.0004f) ? x : r;
}

// phi(x) = -log(tanh(x/2)) with the reference's exact tanh quantization.
__device__ __forceinline__ float phi_f(float x) {
    return -acc_logf(xla_tanhf(0.5f * x));
}

// |sin(argf)| accurate to ~1e-12: dd-pi reduction + odd Taylor to r^15.
__device__ __forceinline__ float abs_sin_acc(float argf) {
    double a = (double)argf;
    double k = rint(a * 0.31830988618379067154);
    double r = fma(-k, 3.141592653589793116, a);
    r = fma(-k, 1.2246467991473531772e-16, r);
    double r2 = r * r;
    double p = -7.6471637318198164759e-13;
    p = fma(r2, p,  1.6059043836821614599e-10);
    p = fma(r2, p, -2.5052108385441718775e-08);
    p = fma(r2, p,  2.7557319223985890653e-06);
    p = fma(r2, p, -1.9841269841269841253e-04);
    p = fma(r2, p,  8.3333333333333332177e-03);
    p = fma(r2, p, -1.6666666666666666574e-01);
    p = fma(r2, p,  1.0);
    return fabsf((float)(r * p));
}

// ---------------- wide scan kernel: H masks + w_vn sign/nz masks --------
__global__ void k_scan(const float* __restrict__ H, const float* __restrict__ w_vn) {
    int t = blockIdx.x * 256 + threadIdx.x;
    const float* base;
    int c;
    bool isH = (t < HW_WORDS);
    if (isH) {
        int m = t / NW; c = t % NW;
        base = H + (size_t)m * TN + c * 32;
    } else {
        int u = t - HW_WORDS;
        int row = u / NW; c = u % NW;
        base = w_vn + (size_t)row * TN + c * 32;
    }
    int nvec = (c == NW - 1) ? 1 : 8;                 // last word: only 4 floats
    unsigned neg = 0, nz = 0;
    for (int v = 0; v < nvec; v++) {
        float4 f = reinterpret_cast<const float4*>(base)[v];
        int k = v * 4;
        neg |= ((f.x < 0.0f) ? 1u : 0u) << k;
        neg |= ((f.y < 0.0f) ? 1u : 0u) << (k + 1);
        neg |= ((f.z < 0.0f) ? 1u : 0u) << (k + 2);
        neg |= ((f.w < 0.0f) ? 1u : 0u) << (k + 3);
        nz  |= ((f.x != 0.0f) ? 1u : 0u) << k;
        nz  |= ((f.y != 0.0f) ? 1u : 0u) << (k + 1);
        nz  |= ((f.z != 0.0f) ? 1u : 0u) << (k + 2);
        nz  |= ((f.w != 0.0f) ? 1u : 0u) << (k + 3);
    }
    if (isH) {
        (&d_hmask[0][0])[t] = nz;
    } else {
        int u = t - HW_WORDS;
        (&d_wneg[0][0][0])[u] = neg;
        (&d_wnz [0][0][0])[u] = nz;
    }
}

// ---------------- k_rows: parallel mask loads + warp prefix-scan ---------
__global__ void k_rows(const float* __restrict__ ex, const float* __restrict__ ez) {
    int gw = (blockIdx.x * blockDim.x + threadIdx.x) >> 5;
    int lane = threadIdx.x & 31;
    if (gw >= MOCC) return;
    int m = gw;

    // parallel loads: lane holds words c=lane and c=lane+32
    unsigned w0 = d_hmask[m][lane];
    unsigned w1 = (lane < NW - 32) ? d_hmask[m][lane + 32] : 0u;
    int p0 = __popc(w0), p1 = __popc(w1);
    // inclusive scans
    int s0 = p0;
    #pragma unroll
    for (int o = 1; o < 32; o <<= 1) { int v = __shfl_up_sync(0xffffffffu, s0, o); if (lane >= o) s0 += v; }
    int total0 = __shfl_sync(0xffffffffu, s0, 31);
    int s1 = p1;
    #pragma unroll
    for (int o = 1; o < 32; o <<= 1) { int v = __shfl_up_sync(0xffffffffu, s1, o); if (lane >= o) s1 += v; }
    int deg = total0 + __shfl_sync(0xffffffffu, s1, 31);
    int b0 = s0 - p0;                 // exclusive base for word lane
    int b1 = total0 + s1 - p1;        // exclusive base for word lane+32
    // place bits (ascending j order preserved)
    unsigned x = w0; int idx = 0;
    while (x) { int bit = __ffs(x) - 1; x &= x - 1;
                int pos = b0 + idx++; if (pos < MAXD) d_row_cols[m][pos] = lane * 32 + bit; }
    x = w1; idx = 0;
    while (x) { int bit = __ffs(x) - 1; x &= x - 1;
                int pos = b1 + idx++; if (pos < MAXD) d_row_cols[m][pos] = (lane + 32) * 32 + bit; }
    if (deg > MAXD) deg = MAXD;
    if (lane == 0) d_row_deg[m] = deg;
    for (int b = 0; b < BB; b++) d_C[b][m][lane] = 0.0f;
    __syncwarp();

    bool act = (lane < deg);
    int col = act ? d_row_cols[m][lane] : 0;
    if (act) {
        int pos = atomicAdd(&d_col_cnt[col], 1);
        if (pos < CMAXD) d_col_edges[col][pos] = m * MAXD + lane;
    }
    // preload syndrome values (independent), then ballots
    float ev[BB];
    #pragma unroll
    for (int b = 0; b < BB; b++)
        ev[b] = act ? ((col < NN) ? ex[b * NN + col] : ez[b * NN + (col - NN)]) : 0.0f;
    #pragma unroll
    for (int b = 0; b < BB; b++) {
        unsigned bal = __ballot_sync(0xffffffffu, act && (ev[b] != 0.0f));
        if (lane == 0) d_synsign[b][m] = (__popc(bal) & 1) ? -1.0f : 1.0f;
    }
}

// ---------------- k_wprep: wedge gather + column sort/pad/reset ----------
__global__ void k_wprep(const float* __restrict__ w_vn) {
    if (blockIdx.x < GATH_BLOCKS) {
        int t = blockIdx.x * 256 + threadIdx.x;
        int slot = t & (MAXD - 1);
        int m    = (t >> 5) & (MOCC - 1);
        int it   = t >> 15;
        float w = 0.0f;
        if (slot < d_row_deg[m]) {
            int col = d_row_cols[m][slot];
            w = w_vn[((size_t)it * MOCC + m) * TN + col];
        }
        d_wedge[it][m][slot] = w;
    } else {
        int j = (blockIdx.x - GATH_BLOCKS) * 256 + threadIdx.x;
        if (j >= TN) return;
        int cnt = d_col_cnt[j];
        if (cnt > CMAXD) cnt = CMAXD;
        int e[CMAXD];
        for (int k = 0; k < cnt; k++) e[k] = d_col_edges[j][k];
        for (int i = 1; i < cnt; i++) {               // ascending m order
            int key = e[i], p = i - 1;
            while (p >= 0 && e[p] > key) { e[p + 1] = e[p]; p--; }
            e[p + 1] = key;
        }
        for (int k = 0; k < cnt; k++) d_col_edges[j][k] = e[k];
        for (int k = cnt; k < PADCD; k++) d_col_edges[j][k] = DUMMY_EDGE;
        d_col_deg[j] = cnt;
        d_col_cnt[j] = 0;                             // reset for next replay
    }
}

// ---------------- CN row update, full-warp fallback (deg>16 rows) --------
__device__ __forceinline__ void cn_solo(int b, int m, int it, float gconst,
                                        int lane, const float* __restrict__ w_cn) {
    const unsigned* wneg = d_wneg[it][m];
    const unsigned* wnz  = d_wnz [it][m];
    int cnt = 0;
    if (it == 0) {
        unsigned GN = (gconst < 0.0f) ? 0xffffffffu : 0u;
        unsigned GZ = (gconst != 0.0f) ? 0xffffffffu : 0u;
        for (int c = lane; c < NW; c += 32)
            cnt += __popc((GN ^ wneg[c]) & GZ & wnz[c]);
    } else {
        const unsigned* gneg = d_gneg[b];
        const unsigned* gnz  = d_gnz [b];
        for (int c = lane; c < NW; c += 32)
            cnt += __popc((gneg[c] ^ wneg[c]) & gnz[c] & wnz[c]);
    }
    for (int o = 16; o; o >>= 1) cnt += __shfl_xor_sync(0xffffffffu, cnt, o);
    int parity = cnt & 1;

    int deg = d_row_deg[m];
    bool act = (lane < deg);
    float V = 0.0f, phi = 0.0f;
    int corr = 0;
    if (act) {
        int j = d_row_cols[m][lane];
        float G = (it == 0) ? gconst : d_Gamma[b][j];
        float Cold = d_C[b][m][lane];
        float w = d_wedge[it][m][lane];
        float x = G - Cold;
        x = fminf(fmaxf(x, -30.0f), 30.0f);
        V = x * w;
        int pneg = (((G < 0.0f) != (w < 0.0f)) && (G != 0.0f) && (w != 0.0f)) ? 1 : 0;
        int vneg = (V < 0.0f) ? 1 : 0;
        corr = pneg ^ vneg;
        if (V != 0.0f) phi = phi_f(fabsf(V));
    }
    unsigned cb = __ballot_sync(0xffffffffu, corr);
    parity ^= (__popc(cb) & 1);

    float A = phi;
    for (int o = 16; o; o >>= 1) A += __shfl_xor_sync(0xffffffffu, A, o);

    if (act) {
        float P = parity ? -1.0f : 1.0f;
        float first = (V < 0.0f) ? -P : P;
        float s2 = A - phi;
        float second = (s2 != 0.0f) ? phi_f(s2) : 0.0f;
        d_C[b][m][lane] = ((first * second) * d_synsign[b][m]) * w_cn[it * MOCC + m];
    }
}

// ---------------- k_bp: 16-CTA clusters, 1 CN task per warp --------------
__global__ void __launch_bounds__(BPTHR, 1) __cluster_dims__(CLSZ, 1, 1)
k_bp(const float* __restrict__ ex, const float* __restrict__ ez,
     const float* __restrict__ ep,
     const float* __restrict__ Gx, const float* __restrict__ Gz,
     const float* __restrict__ w_llr, const float* __restrict__ w_cn,
     float* __restrict__ out)
{
    const int tid  = threadIdx.x;
    const int lane = tid & 31;
    const int b    = blockIdx.x / CLSZ;               // batch for this cluster
    const int rank = blockIdx.x % CLSZ;               // cta rank in cluster
    const int cw   = rank * (BPTHR / 32) + (tid >> 5);  // cluster warp id 0..511
    const int half = lane >> 4;
    const int hl   = lane & 15;

    // ---- prologue: cache static per-warp state in registers ----
    // CN task: warp cw handles rows 2cw, 2cw+1 (cw < 512 always)
    int  cn_m, cn_j;
    bool cn_act, cn_packed;
    float cn_syn, Creg;
    {
        int m1 = 2 * cw, m2 = 2 * cw + 1;
        int deg1 = d_row_deg[m1], deg2 = d_row_deg[m2];
        cn_packed = (deg1 <= 16 && deg2 <= 16);
        int m   = half ? m2 : m1;
        int deg = half ? deg2 : deg1;
        cn_m   = m;
        cn_act = (hl < deg);
        cn_j   = cn_act ? d_row_cols[m][hl] : 0;
        cn_syn = d_synsign[b][m];
        Creg   = 0.0f;
    }
    // VN task: warp cw < 56 handles word-group jw = cw
    int vj = cw * 32 + lane;
    bool vin = (cw < NW) && (vj < TN);
    int  ve[PADCD];
    int  vcd = 0;
    bool vmask = false;
    if (vin) {
        vcd = d_col_deg[vj];
        #pragma unroll
        for (int k = 0; k < PADCD; k++) ve[k] = d_col_edges[vj][k];
        float mk = (vj < NN) ? ex[b * NN + vj] : ez[b * NN + (vj - NN)];
        vmask = (mk == 1.0f);
    } else {
        #pragma unroll
        for (int k = 0; k < PADCD; k++) ve[k] = DUMMY_EDGE;
    }

    float e0  = ep[0];
    float llr = acc_logf(__fdiv_rn(1.0f - e0, e0));
    float gconst = llr * w_llr[0];

    for (int it = 0; it < TT; it++) {
        // ---- CN phase: 1 packed task per warp ----
        if (cn_packed) {
            int m = cn_m;
            float w   = cn_act ? d_wedge[it][m][hl] : 0.0f;
            float wcn = w_cn[it * MOCC + m];
            const unsigned* wneg = d_wneg[it][m];
            const unsigned* wnz  = d_wnz [it][m];
            int cnt = 0;
            if (it == 0) {
                unsigned GN = (gconst < 0.0f) ? 0xffffffffu : 0u;
                unsigned GZ = (gconst != 0.0f) ? 0xffffffffu : 0u;
                for (int c = hl; c < NW; c += 16)
                    cnt += __popc((GN ^ wneg[c]) & GZ & wnz[c]);
            } else {
                const unsigned* gneg = d_gneg[b];
                const unsigned* gnz  = d_gnz [b];
                for (int c = hl; c < NW; c += 16)
                    cnt += __popc((gneg[c] ^ wneg[c]) & gnz[c] & wnz[c]);
            }
            for (int o = 8; o; o >>= 1) cnt += __shfl_xor_sync(0xffffffffu, cnt, o);
            int parity = cnt & 1;

            float V = 0.0f, phi = 0.0f;
            int corr = 0;
            if (cn_act) {
                float G = (it == 0) ? gconst : d_Gamma[b][cn_j];
                float x = G - Creg;
                x = fminf(fmaxf(x, -30.0f), 30.0f);
                V = x * w;
                int pneg = (((G < 0.0f) != (w < 0.0f)) && (G != 0.0f) && (w != 0.0f)) ? 1 : 0;
                int vneg = (V < 0.0f) ? 1 : 0;
                corr = pneg ^ vneg;
                if (V != 0.0f) phi = phi_f(fabsf(V));
            }
            unsigned cb = __ballot_sync(0xffffffffu, corr);
            unsigned hmask = half ? (cb >> 16) : (cb & 0xFFFFu);
            parity ^= (__popc(hmask) & 1);

            float A = phi;   // half-tree == solo tree for deg<=16 (zero pad)
            for (int o = 8; o; o >>= 1) A += __shfl_xor_sync(0xffffffffu, A, o);

            if (cn_act) {
                float P = parity ? -1.0f : 1.0f;
                float first = (V < 0.0f) ? -P : P;
                float s2 = A - phi;
                float second = (s2 != 0.0f) ? phi_f(s2) : 0.0f;
                float outv = ((first * second) * cn_syn) * wcn;
                Creg = outv;
                d_C[b][m][hl] = outv;
            }
        } else {
            cn_solo(b, 2 * cw,     it, gconst, lane, w_cn);
            cn_solo(b, 2 * cw + 1, it, gconst, lane, w_cn);
        }
        cbar();

        // ---- VN phase (1 task/warp) + loss terms for it-1 ----
        float wl = w_llr[it + 1];
        if (cw < NW) {
            float g = 0.0f;
            if (vin) {
                const float* Cb = &d_C[b][0][0];
                float sum = 0.0f;
                #pragma unroll
                for (int k = 0; k < PADCD; k++) sum += Cb[ve[k]];
                if (vcd > PADCD)
                    for (int k = PADCD; k < vcd; k++) sum += Cb[d_col_edges[vj][k]];
                g = llr * wl + sum;
                d_Gamma[b][vj] = g;
                float pmv = 0.0f;
                if (vmask) pmv = __fdiv_rn(1.0f, 1.0f + acc_expf(g));
                d_pm2[it & 1][b][vj] = pmv;
            }
            unsigned bneg = __ballot_sync(0xffffffffu, vin && (g < 0.0f));
            unsigned bnz  = __ballot_sync(0xffffffffu, vin && (g != 0.0f));
            if (lane == 0) { d_gneg[b][cw] = bneg; d_gnz[b][cw] = bnz; }
        } else if (it > 0 && cw < NW + LT2) {
            int k2 = cw - NW;
            int buf = (it - 1) & 1;
            const float* Grow  = (k2 < KK) ? Gx + (size_t)k2 * NN : Gz + (size_t)(k2 - KK) * NN;
            const float* pmrow = (k2 < KK) ? &d_pm2[buf][b][0] : &d_pm2[buf][b][NN];
            float s = 0.0f;
            for (int n = lane; n < NN; n += 32) s += pmrow[n] * Grow[n];
            for (int o = 16; o; o >>= 1) s += __shfl_xor_sync(0xffffffffu, s, o);
            if (lane == 0) d_lossterm2[b][it - 1][k2] = abs_sin_acc(1.5707964f * s);
        }
        cbar();
    }

    // ---- epilogue: loss terms for it = TT-1 (pm buffer (TT-1)&1) ----
    if (cw < LT2) {
        int k2 = cw;
        int buf = (TT - 1) & 1;
        const float* Grow  = (k2 < KK) ? Gx + (size_t)k2 * NN : Gz + (size_t)(k2 - KK) * NN;
        const float* pmrow = (k2 < KK) ? &d_pm2[buf][b][0] : &d_pm2[buf][b][NN];
        float s = 0.0f;
        for (int n = lane; n < NN; n += 32) s += pmrow[n] * Grow[n];
        for (int o = 16; o; o >>= 1) s += __shfl_xor_sync(0xffffffffu, s, o);
        if (lane == 0) d_lossterm2[b][TT - 1][k2] = abs_sin_acc(1.5707964f * s);
    }
    cbar();

    // ---- per-batch reduction + cross-cluster finish ----
    if (rank == 0 && tid == 0) {
        float v[TT];
        for (int i = 0; i < TT; i++) {
            float tsum = 0.0f;
            for (int k = 0; k < LT2; k++) tsum += d_lossterm2[b][i][k];
            v[i] = tsum;
        }
        float best = v[0]; int bi = 0;
        for (int i = 1; i < TT; i++) if (v[i] < best) { best = v[i]; bi = i; }
        float cs = 0.0f;
        for (int i = 0; i <= bi; i++) cs += v[i];
        d_lossb[b] = __fdiv_rn(cs, (float)(bi + 1));
        __threadfence();
        int prev = atomicAdd(&g_done, 1);
        if (prev == BB - 1) {                         // last cluster finishes
            __threadfence();
            float tot = 0.0f;
            for (int bb = 0; bb < BB; bb++) tot += d_lossb[bb];
            out[0] = tot * 0.125f;
            g_done = 0;                               // reset for next replay
            __threadfence();
        }
    }
}

// ---------------- launch ----------------
extern "C" void kernel_launch(void* const* d_in, const int* in_sizes, int n_in,
                              void* d_out, int out_size) {
    const float* ex    = (const float*)d_in[0];
    const float* ez    = (const float*)d_in[1];
    const float* ep    = (const float*)d_in[2];
    const float* H     = (const float*)d_in[3];
    const float* Gx    = (const float*)d_in[6];
    const float* Gz    = (const float*)d_in[7];
    const float* w_vn  = (const float*)d_in[8];
    const float* w_llr = (const float*)d_in[9];
    const float* w_cn  = (const float*)d_in[10];
    float* out = (float*)d_out;

    // allow 16-CTA (non-portable) clusters; attribute call, not a stream op
    cudaFuncSetAttribute((const void*)k_bp,
                         cudaFuncAttributeNonPortableClusterSizeAllowed, 1);

    k_scan <<<SCAN_WORDS / 256, 256>>>(H, w_vn);
    k_rows <<<MOCC / 8, 256>>>(ex, ez);
    k_wprep<<<GATH_BLOCKS + SORT_BLOCKS, 256>>>(w_vn);
    k_bp   <<<BB * CLSZ, BPTHR>>>(ex, ez, ep, Gx, Gz, w_llr, w_cn, out);
}

// round 15
// speedup vs baseline: 1.3951x; 1.3951x over previous
#include <cuda_runtime.h>
#include <cuda_bf16.h>
#include <cstdint>

#define NN   882
#define TN   1764
#define MOCC 1024
#define BB   8
#define TT   6
#define KK   24
#define MAXD 32
#define CMAXD 24
#define PADCD 16
#define NW   56                      // ceil(1764/32)
#define DUMMY_EDGE (MOCC * MAXD)     // points at always-zero padding row of d_C

#define HW_WORDS  (MOCC * NW)        // 57344
#define WW_WORDS  (TT * MOCC * NW)   // 344064
#define SCAN_WORDS (HW_WORDS + WW_WORDS)             // 401408 = 1568*256
#define GATH_BLOCKS (TT * MOCC * MAXD / 256)         // 768
#define SORT_BLOCKS ((TN + 255) / 256)               // 7

// cluster kernel geometry: 8 clusters (1/batch) x 8 CTAs x 1024 threads
#define CLSZ   8
#define BPTHR  1024
#define NCW    (CLSZ * (BPTHR / 32))  // 256 warps per cluster
#define LT2    (2 * KK)               // 48 per-batch loss-term tasks

// ---------------- device scratch (no allocations allowed) ----------------
__device__ unsigned d_hmask[MOCC][NW];        // H nonzero bitmasks
__device__ int   d_row_deg[MOCC];
__device__ int   d_row_cols[MOCC][MAXD];
__device__ int   d_col_cnt[TN];               // atomic counters (self-resetting)
__device__ int   d_col_deg[TN];
__device__ int   d_col_edges[TN][CMAXD];      // edge idx = m*MAXD + slot (sorted, padded)
__device__ float d_C[BB][MOCC + 1][MAXD];     // c2v messages; row MOCC = permanent zeros
__device__ float d_wedge[TT][MOCC][MAXD];     // pre-gathered w_vn on edges
__device__ float d_Gamma[BB][TN];
__device__ float d_pm2[2][BB][TN];            // double-buffered masked prob
__device__ float d_synsign[BB][MOCC];         // (1 - 2*syn)
__device__ float d_lossterm2[BB][TT][LT2];
__device__ float d_lossb[BB];                 // per-batch final scalar
__device__ int   g_done;                      // cross-cluster finish counter
__device__ unsigned d_wneg[TT][MOCC][NW];     // sign bitmasks of w_vn[0..5]
__device__ unsigned d_wnz [TT][MOCC][NW];
__device__ unsigned d_gneg[BB][NW];           // sign bitmasks of Gamma
__device__ unsigned d_gnz [BB][NW];

// cluster barrier: arrive = .release, wait = .acquire (cluster scope)
__device__ __forceinline__ void cbar() {
    asm volatile("barrier.cluster.arrive.aligned;" ::: "memory");
    asm volatile("barrier.cluster.wait.aligned;" ::: "memory");
}

// ---------------- accurate fp32 math (flag-independent; rn division) ----
__device__ __forceinline__ float acc_expf(float x) {
    if (x < -87.0f) return 0.0f;
    if (x >  88.0f) return __int_as_float(0x7f800000);
    float kf = rintf(x * 1.4426950408889634f);
    float r  = fmaf(-kf, 0.693359375f, x);
    r = fmaf(kf, 2.12194440e-4f, r);
    float p = 1.9841270e-4f;
    p = fmaf(r, p, 1.3888889e-3f);
    p = fmaf(r, p, 8.3333333e-3f);
    p = fmaf(r, p, 4.1666667e-2f);
    p = fmaf(r, p, 1.6666667e-1f);
    p = fmaf(r, p, 0.5f);
    p = fmaf(r, p, 1.0f);
    p = fmaf(r, p, 1.0f);
    int k = (int)kf;
    float sc = __int_as_float((k + 127) << 23);
    return p * sc;
}

// log for t>0; returns EXACT +-0.0f at t==1.0f (load-bearing for phi semantics)
__device__ __forceinline__ float acc_logf(float t) {
    int ix = __float_as_int(t);
    int e  = ((ix >> 23) & 0xff) - 127;
    float m = __int_as_float((ix & 0x007fffff) | 0x3f800000);   // [1,2)
    if (m > 1.4142135f) { m *= 0.5f; e += 1; }
    float f  = m - 1.0f;
    float s  = __fdiv_rn(f, 2.0f + f);
    float s2 = s * s;
    float p  = fmaf(s2, 0.11111111f, 0.14285714f);
    p = fmaf(s2, p, 0.2f);
    p = fmaf(s2, p, 0.33333333f);
    float lm = fmaf(2.0f * s, s2 * p, 2.0f * s);
    float r  = fmaf((float)e, 0.693359375f, lm);
    r = fmaf((float)e, -2.12194440e-4f, r);
    return r;
}

// XLA / Eigen fast-tanh (f32, FMA variant) — bit-matches jnp.tanh on GPU.
__device__ __forceinline__ float xla_tanhf(float x) {
    float ax = fabsf(x);
    float xc = fminf(fmaxf(x, -7.99881172180175781f), 7.99881172180175781f);
    float x2 = xc * xc;
    float p = -2.76076847742355e-16f;
    p = fmaf(x2, p,  2.00018790482477e-13f);
    p = fmaf(x2, p, -8.60467152213735e-11f);
    p = fmaf(x2, p,  5.12229709037114e-08f);
    p = fmaf(x2, p,  1.48572235717979e-05f);
    p = fmaf(x2, p,  6.37261928875436e-04f);
    p = fmaf(x2, p,  4.89352455891786e-03f);
    float num = xc * p;
    float q = 1.19825839466702e-06f;
    q = fmaf(x2, q, 1.18534705686654e-04f);
    q = fmaf(x2, q, 2.26843463243900e-03f);
    q = fmaf(x2, q, 4.89352518554385e-03f);
    float r = __fdiv_rn(num, q);
    return (ax < 0.0004f) ? x : r;
}

// phi(x) = -log(tanh(x/2)) with the reference's exact tanh quantization.
__device__ __forceinline__ float phi_f(float x) {
    return -acc_logf(xla_tanhf(0.5f * x));
}

// |sin(argf)| accurate to ~1e-12: dd-pi reduction + odd Taylor to r^15.
__device__ __forceinline__ float abs_sin_acc(float argf) {
    double a = (double)argf;
    double k = rint(a * 0.31830988618379067154);
    double r = fma(-k, 3.141592653589793116, a);
    r = fma(-k, 1.2246467991473531772e-16, r);
    double r2 = r * r;
    double p = -7.6471637318198164759e-13;
    p = fma(r2, p,  1.6059043836821614599e-10);
    p = fma(r2, p, -2.5052108385441718775e-08);
    p = fma(r2, p,  2.7557319223985890653e-06);
    p = fma(r2, p, -1.9841269841269841253e-04);
    p = fma(r2, p,  8.3333333333333332177e-03);
    p = fma(r2, p, -1.6666666666666666574e-01);
    p = fma(r2, p,  1.0);
    return fabsf((float)(r * p));
}

// ---------------- wide scan kernel: H masks + w_vn sign/nz masks --------
__global__ void k_scan(const float* __restrict__ H, const float* __restrict__ w_vn) {
    int t = blockIdx.x * 256 + threadIdx.x;
    const float* base;
    int c;
    bool isH = (t < HW_WORDS);
    if (isH) {
        int m = t / NW; c = t % NW;
        base = H + (size_t)m * TN + c * 32;
    } else {
        int u = t - HW_WORDS;
        int row = u / NW; c = u % NW;
        base = w_vn + (size_t)row * TN + c * 32;
    }
    int nvec = (c == NW - 1) ? 1 : 8;                 // last word: only 4 floats
    unsigned neg = 0, nz = 0;
    for (int v = 0; v < nvec; v++) {
        float4 f = reinterpret_cast<const float4*>(base)[v];
        int k = v * 4;
        neg |= ((f.x < 0.0f) ? 1u : 0u) << k;
        neg |= ((f.y < 0.0f) ? 1u : 0u) << (k + 1);
        neg |= ((f.z < 0.0f) ? 1u : 0u) << (k + 2);
        neg |= ((f.w < 0.0f) ? 1u : 0u) << (k + 3);
        nz  |= ((f.x != 0.0f) ? 1u : 0u) << k;
        nz  |= ((f.y != 0.0f) ? 1u : 0u) << (k + 1);
        nz  |= ((f.z != 0.0f) ? 1u : 0u) << (k + 2);
        nz  |= ((f.w != 0.0f) ? 1u : 0u) << (k + 3);
    }
    if (isH) {
        (&d_hmask[0][0])[t] = nz;
    } else {
        int u = t - HW_WORDS;
        (&d_wneg[0][0][0])[u] = neg;
        (&d_wnz [0][0][0])[u] = nz;
    }
}

// ---------------- k_rows: parallel mask loads + warp prefix-scan ---------
__global__ void k_rows(const float* __restrict__ ex, const float* __restrict__ ez) {
    int gw = (blockIdx.x * blockDim.x + threadIdx.x) >> 5;
    int lane = threadIdx.x & 31;
    if (gw >= MOCC) return;
    int m = gw;

    unsigned w0 = d_hmask[m][lane];
    unsigned w1 = (lane < NW - 32) ? d_hmask[m][lane + 32] : 0u;
    int p0 = __popc(w0), p1 = __popc(w1);
    int s0 = p0;
    #pragma unroll
    for (int o = 1; o < 32; o <<= 1) { int v = __shfl_up_sync(0xffffffffu, s0, o); if (lane >= o) s0 += v; }
    int total0 = __shfl_sync(0xffffffffu, s0, 31);
    int s1 = p1;
    #pragma unroll
    for (int o = 1; o < 32; o <<= 1) { int v = __shfl_up_sync(0xffffffffu, s1, o); if (lane >= o) s1 += v; }
    int deg = total0 + __shfl_sync(0xffffffffu, s1, 31);
    int b0 = s0 - p0;
    int b1 = total0 + s1 - p1;
    unsigned x = w0; int idx = 0;
    while (x) { int bit = __ffs(x) - 1; x &= x - 1;
                int pos = b0 + idx++; if (pos < MAXD) d_row_cols[m][pos] = lane * 32 + bit; }
    x = w1; idx = 0;
    while (x) { int bit = __ffs(x) - 1; x &= x - 1;
                int pos = b1 + idx++; if (pos < MAXD) d_row_cols[m][pos] = (lane + 32) * 32 + bit; }
    if (deg > MAXD) deg = MAXD;
    if (lane == 0) d_row_deg[m] = deg;
    for (int b = 0; b < BB; b++) d_C[b][m][lane] = 0.0f;
    __syncwarp();

    bool act = (lane < deg);
    int col = act ? d_row_cols[m][lane] : 0;
    if (act) {
        int pos = atomicAdd(&d_col_cnt[col], 1);
        if (pos < CMAXD) d_col_edges[col][pos] = m * MAXD + lane;
    }
    float ev[BB];
    #pragma unroll
    for (int b = 0; b < BB; b++)
        ev[b] = act ? ((col < NN) ? ex[b * NN + col] : ez[b * NN + (col - NN)]) : 0.0f;
    #pragma unroll
    for (int b = 0; b < BB; b++) {
        unsigned bal = __ballot_sync(0xffffffffu, act && (ev[b] != 0.0f));
        if (lane == 0) d_synsign[b][m] = (__popc(bal) & 1) ? -1.0f : 1.0f;
    }
}

// ---------------- k_wprep: wedge gather + column sort/pad/reset ----------
__global__ void k_wprep(const float* __restrict__ w_vn) {
    if (blockIdx.x < GATH_BLOCKS) {
        int t = blockIdx.x * 256 + threadIdx.x;
        int slot = t & (MAXD - 1);
        int m    = (t >> 5) & (MOCC - 1);
        int it   = t >> 15;
        float w = 0.0f;
        if (slot < d_row_deg[m]) {
            int col = d_row_cols[m][slot];
            w = w_vn[((size_t)it * MOCC + m) * TN + col];
        }
        d_wedge[it][m][slot] = w;
    } else {
        int j = (blockIdx.x - GATH_BLOCKS) * 256 + threadIdx.x;
        if (j >= TN) return;
        int cnt = d_col_cnt[j];
        if (cnt > CMAXD) cnt = CMAXD;
        int e[CMAXD];
        for (int k = 0; k < cnt; k++) e[k] = d_col_edges[j][k];
        for (int i = 1; i < cnt; i++) {               // ascending m order
            int key = e[i], p = i - 1;
            while (p >= 0 && e[p] > key) { e[p + 1] = e[p]; p--; }
            e[p + 1] = key;
        }
        for (int k = 0; k < cnt; k++) d_col_edges[j][k] = e[k];
        for (int k = cnt; k < PADCD; k++) d_col_edges[j][k] = DUMMY_EDGE;
        d_col_deg[j] = cnt;
        d_col_cnt[j] = 0;                             // reset for next replay
    }
}

// ---------------- CN row update, full-warp fallback (deg>16 rows) --------
__device__ __forceinline__ void cn_solo(int b, int m, int it, float gconst,
                                        int lane, const float* __restrict__ w_cn) {
    const unsigned* wneg = d_wneg[it][m];
    const unsigned* wnz  = d_wnz [it][m];
    int cnt = 0;
    if (it == 0) {
        unsigned GN = (gconst < 0.0f) ? 0xffffffffu : 0u;
        unsigned GZ = (gconst != 0.0f) ? 0xffffffffu : 0u;
        for (int c = lane; c < NW; c += 32)
            cnt += __popc((GN ^ wneg[c]) & GZ & wnz[c]);
    } else {
        const unsigned* gneg = d_gneg[b];
        const unsigned* gnz  = d_gnz [b];
        for (int c = lane; c < NW; c += 32)
            cnt += __popc((gneg[c] ^ wneg[c]) & gnz[c] & wnz[c]);
    }
    for (int o = 16; o; o >>= 1) cnt += __shfl_xor_sync(0xffffffffu, cnt, o);
    int parity = cnt & 1;

    int deg = d_row_deg[m];
    bool act = (lane < deg);
    float V = 0.0f, phi = 0.0f;
    int corr = 0;
    if (act) {
        int j = d_row_cols[m][lane];
        float G = (it == 0) ? gconst : d_Gamma[b][j];
        float Cold = d_C[b][m][lane];
        float w = d_wedge[it][m][lane];
        float x = G - Cold;
        x = fminf(fmaxf(x, -30.0f), 30.0f);
        V = x * w;
        int pneg = (((G < 0.0f) != (w < 0.0f)) && (G != 0.0f) && (w != 0.0f)) ? 1 : 0;
        int vneg = (V < 0.0f) ? 1 : 0;
        corr = pneg ^ vneg;
        if (V != 0.0f) phi = phi_f(fabsf(V));
    }
    unsigned cb = __ballot_sync(0xffffffffu, corr);
    parity ^= (__popc(cb) & 1);

    float A = phi;
    for (int o = 16; o; o >>= 1) A += __shfl_xor_sync(0xffffffffu, A, o);

    if (act) {
        float P = parity ? -1.0f : 1.0f;
        float first = (V < 0.0f) ? -P : P;
        float s2 = A - phi;
        float second = (s2 != 0.0f) ? phi_f(s2) : 0.0f;
        d_C[b][m][lane] = ((first * second) * d_synsign[b][m]) * w_cn[it * MOCC + m];
    }
}

// ---------------- k_bp: 8-CTA clusters, staged 2-task CN -----------------
__global__ void __launch_bounds__(BPTHR, 1) __cluster_dims__(CLSZ, 1, 1)
k_bp(const float* __restrict__ ex, const float* __restrict__ ez,
     const float* __restrict__ ep,
     const float* __restrict__ Gx, const float* __restrict__ Gz,
     const float* __restrict__ w_llr, const float* __restrict__ w_cn,
     float* __restrict__ out)
{
    const int tid  = threadIdx.x;
    const int lane = tid & 31;
    const int b    = blockIdx.x / CLSZ;               // batch for this cluster
    const int rank = blockIdx.x % CLSZ;               // cta rank in cluster
    const int cw   = rank * (BPTHR / 32) + (tid >> 5);  // cluster warp id 0..255
    const int half = lane >> 4;
    const int hl   = lane & 15;

    // ---- prologue: cache static per-warp state in registers ----
    int  cn_m[2], cn_j[2];
    bool cn_act[2], cn_packed[2];
    float cn_syn[2], Creg[2];
    #pragma unroll
    for (int s = 0; s < 2; s++) {
        int t = cw + s * 256;
        int m1 = 2 * t, m2 = 2 * t + 1;
        int deg1 = d_row_deg[m1], deg2 = d_row_deg[m2];
        cn_packed[s] = (deg1 <= 16 && deg2 <= 16);
        int m   = half ? m2 : m1;
        int deg = half ? deg2 : deg1;
        cn_m[s]   = m;
        cn_act[s] = (hl < deg);
        cn_j[s]   = cn_act[s] ? d_row_cols[m][hl] : 0;
        cn_syn[s] = d_synsign[b][m];
        Creg[s]   = 0.0f;
    }
    // VN task
    int vj = cw * 32 + lane;
    bool vin = (cw < NW) && (vj < TN);
    int  ve[PADCD];
    int  vcd = 0;
    bool vmask = false;
    if (vin) {
        vcd = d_col_deg[vj];
        #pragma unroll
        for (int k = 0; k < PADCD; k++) ve[k] = d_col_edges[vj][k];
        float mk = (vj < NN) ? ex[b * NN + vj] : ez[b * NN + (vj - NN)];
        vmask = (mk == 1.0f);
    } else {
        #pragma unroll
        for (int k = 0; k < PADCD; k++) ve[k] = DUMMY_EDGE;
    }

    float e0  = ep[0];
    float llr = acc_logf(__fdiv_rn(1.0f - e0, e0));
    float gconst = llr * w_llr[0];

    for (int it = 0; it < TT; it++) {
        // ---- CN phase: stage 1 — issue both tasks' loads + popc ----
        bool both_packed = cn_packed[0] && cn_packed[1];
        if (both_packed) {
            int   cnt[2];
            float wreg[2], wcnreg[2], Greg[2];
            #pragma unroll
            for (int s = 0; s < 2; s++) {
                int m = cn_m[s];
                wreg[s]   = cn_act[s] ? d_wedge[it][m][hl] : 0.0f;
                wcnreg[s] = w_cn[it * MOCC + m];
                Greg[s]   = (it == 0) ? gconst : (cn_act[s] ? d_Gamma[b][cn_j[s]] : 0.0f);
                const unsigned* wneg = d_wneg[it][m];
                const unsigned* wnz  = d_wnz [it][m];
                int c0 = 0;
                if (it == 0) {
                    unsigned GN = (gconst < 0.0f) ? 0xffffffffu : 0u;
                    unsigned GZ = (gconst != 0.0f) ? 0xffffffffu : 0u;
                    for (int c = hl; c < NW; c += 16)
                        c0 += __popc((GN ^ wneg[c]) & GZ & wnz[c]);
                } else {
                    const unsigned* gneg = d_gneg[b];
                    const unsigned* gnz  = d_gnz [b];
                    for (int c = hl; c < NW; c += 16)
                        c0 += __popc((gneg[c] ^ wneg[c]) & gnz[c] & wnz[c]);
                }
                cnt[s] = c0;
            }
            // ---- stage 2: complete each task (reductions + phi + store) ----
            #pragma unroll
            for (int s = 0; s < 2; s++) {
                int c0 = cnt[s];
                for (int o = 8; o; o >>= 1) c0 += __shfl_xor_sync(0xffffffffu, c0, o);
                int parity = c0 & 1;

                float V = 0.0f, phi = 0.0f;
                int corr = 0;
                if (cn_act[s]) {
                    float G = Greg[s];
                    float x = G - Creg[s];
                    x = fminf(fmaxf(x, -30.0f), 30.0f);
                    V = x * wreg[s];
                    int pneg = (((G < 0.0f) != (wreg[s] < 0.0f)) && (G != 0.0f) && (wreg[s] != 0.0f)) ? 1 : 0;
                    int vneg = (V < 0.0f) ? 1 : 0;
                    corr = pneg ^ vneg;
                    if (V != 0.0f) phi = phi_f(fabsf(V));
                }
                unsigned cb = __ballot_sync(0xffffffffu, corr);
                unsigned hmask = half ? (cb >> 16) : (cb & 0xFFFFu);
                parity ^= (__popc(hmask) & 1);

                float A = phi;   // half-tree == solo tree for deg<=16 (zero pad)
                for (int o = 8; o; o >>= 1) A += __shfl_xor_sync(0xffffffffu, A, o);

                if (cn_act[s]) {
                    float P = parity ? -1.0f : 1.0f;
                    float first = (V < 0.0f) ? -P : P;
                    float s2 = A - phi;
                    float second = (s2 != 0.0f) ? phi_f(s2) : 0.0f;
                    float outv = ((first * second) * cn_syn[s]) * wcnreg[s];
                    Creg[s] = outv;
                    d_C[b][cn_m[s]][hl] = outv;
                }
            }
        } else {
            #pragma unroll
            for (int s = 0; s < 2; s++) {
                int t = cw + s * 256;
                cn_solo(b, 2 * t,     it, gconst, lane, w_cn);
                cn_solo(b, 2 * t + 1, it, gconst, lane, w_cn);
            }
        }
        cbar();

        // ---- VN phase (1 task/warp) + loss terms for it-1 ----
        float wl = w_llr[it + 1];
        if (cw < NW) {
            float g = 0.0f;
            if (vin) {
                const float* Cb = &d_C[b][0][0];
                float sum = 0.0f;
                #pragma unroll
                for (int k = 0; k < PADCD; k++) sum += Cb[ve[k]];
                if (vcd > PADCD)
                    for (int k = PADCD; k < vcd; k++) sum += Cb[d_col_edges[vj][k]];
                g = llr * wl + sum;
                d_Gamma[b][vj] = g;
                float pmv = 0.0f;
                if (vmask) pmv = __fdiv_rn(1.0f, 1.0f + acc_expf(g));
                d_pm2[it & 1][b][vj] = pmv;
            }
            unsigned bneg = __ballot_sync(0xffffffffu, vin && (g < 0.0f));
            unsigned bnz  = __ballot_sync(0xffffffffu, vin && (g != 0.0f));
            if (lane == 0) { d_gneg[b][cw] = bneg; d_gnz[b][cw] = bnz; }
        } else if (it > 0 && cw < NW + LT2) {
            int k2 = cw - NW;
            int buf = (it - 1) & 1;
            const float* Grow  = (k2 < KK) ? Gx + (size_t)k2 * NN : Gz + (size_t)(k2 - KK) * NN;
            const float* pmrow = (k2 < KK) ? &d_pm2[buf][b][0] : &d_pm2[buf][b][NN];
            float s = 0.0f;
            for (int n = lane; n < NN; n += 32) s += pmrow[n] * Grow[n];
            for (int o = 16; o; o >>= 1) s += __shfl_xor_sync(0xffffffffu, s, o);
            if (lane == 0) d_lossterm2[b][it - 1][k2] = abs_sin_acc(1.5707964f * s);
        }
        cbar();
    }

    // ---- epilogue: loss terms for it = TT-1 (pm buffer (TT-1)&1) ----
    if (cw < LT2) {
        int k2 = cw;
        int buf = (TT - 1) & 1;
        const float* Grow  = (k2 < KK) ? Gx + (size_t)k2 * NN : Gz + (size_t)(k2 - KK) * NN;
        const float* pmrow = (k2 < KK) ? &d_pm2[buf][b][0] : &d_pm2[buf][b][NN];
        float s = 0.0f;
        for (int n = lane; n < NN; n += 32) s += pmrow[n] * Grow[n];
        for (int o = 16; o; o >>= 1) s += __shfl_xor_sync(0xffffffffu, s, o);
        if (lane == 0) d_lossterm2[b][TT - 1][k2] = abs_sin_acc(1.5707964f * s);
    }
    cbar();

    // ---- per-batch reduction + cross-cluster finish ----
    if (rank == 0 && tid == 0) {
        float v[TT];
        for (int i = 0; i < TT; i++) {
            float tsum = 0.0f;
            for (int k = 0; k < LT2; k++) tsum += d_lossterm2[b][i][k];
            v[i] = tsum;
        }
        float best = v[0]; int bi = 0;
        for (int i = 1; i < TT; i++) if (v[i] < best) { best = v[i]; bi = i; }
        float cs = 0.0f;
        for (int i = 0; i <= bi; i++) cs += v[i];
        d_lossb[b] = __fdiv_rn(cs, (float)(bi + 1));
        __threadfence();
        int prev = atomicAdd(&g_done, 1);
        if (prev == BB - 1) {                         // last cluster finishes
            __threadfence();
            float tot = 0.0f;
            for (int bb = 0; bb < BB; bb++) tot += d_lossb[bb];
            out[0] = tot * 0.125f;
            g_done = 0;                               // reset for next replay
            __threadfence();
        }
    }
}

// ---------------- launch ----------------
extern "C" void kernel_launch(void* const* d_in, const int* in_sizes, int n_in,
                              void* d_out, int out_size) {
    const float* ex    = (const float*)d_in[0];
    const float* ez    = (const float*)d_in[1];
    const float* ep    = (const float*)d_in[2];
    const float* H     = (const float*)d_in[3];
    const float* Gx    = (const float*)d_in[6];
    const float* Gz    = (const float*)d_in[7];
    const float* w_vn  = (const float*)d_in[8];
    const float* w_llr = (const float*)d_in[9];
    const float* w_cn  = (const float*)d_in[10];
    float* out = (float*)d_out;

    k_scan <<<SCAN_WORDS / 256, 256>>>(H, w_vn);
    k_rows <<<MOCC / 8, 256>>>(ex, ez);
    k_wprep<<<GATH_BLOCKS + SORT_BLOCKS, 256>>>(w_vn);
    k_bp   <<<BB * CLSZ, BPTHR>>>(ex, ez, ep, Gx, Gz, w_llr, w_cn, out);
}

// round 16
// speedup vs baseline: 1.4976x; 1.0735x over previous
#include <cuda_runtime.h>
#include <cuda_bf16.h>
#include <cstdint>

#define NN   882
#define TN   1764
#define MOCC 1024
#define BB   8
#define TT   6
#define KK   24
#define MAXD 32
#define CMAXD 24
#define PADCD 16
#define NW   56                      // ceil(1764/32)
#define NWP  64                      // padded mask words (57..63 stay zero)
#define DUMMY_EDGE (MOCC * MAXD)     // points at always-zero padding row of d_C

#define HW_WORDS  (MOCC * NW)        // 57344
#define WW_WORDS  (TT * MOCC * NW)   // 344064
#define SCAN_WORDS (HW_WORDS + WW_WORDS)             // 401408 = 1568*256
#define GATH_BLOCKS (TT * MOCC * MAXD / 256)         // 768
#define SORT_BLOCKS ((TN + 255) / 256)               // 7

// cluster kernel geometry: 8 clusters (1/batch) x 8 CTAs x 1024 threads
#define CLSZ   8
#define BPTHR  1024
#define NCW    (CLSZ * (BPTHR / 32))  // 256 warps per cluster
#define LT2    (2 * KK)               // 48 per-batch loss-term tasks

// ---------------- device scratch (no allocations allowed) ----------------
__device__ unsigned d_hmask[MOCC][NW];        // H nonzero bitmasks
__device__ int   d_row_deg[MOCC];
__device__ int   d_row_cols[MOCC][MAXD];
__device__ int   d_col_cnt[TN];               // atomic counters (self-resetting)
__device__ int   d_col_deg[TN];
__device__ int   d_col_edges[TN][CMAXD];      // edge idx = m*MAXD + slot (sorted, padded)
__device__ float d_C[BB][MOCC + 1][MAXD];     // c2v messages; row MOCC = permanent zeros
__device__ float d_wedge[TT][MOCC][MAXD];     // pre-gathered w_vn on edges
__device__ float d_Gamma[BB][TN];
__device__ float d_pm2[2][BB][TN];            // double-buffered masked prob
__device__ float d_synsign[BB][MOCC];         // (1 - 2*syn)
__device__ float d_lossterm2[BB][TT][LT2];
__device__ float d_lossb[BB];                 // per-batch final scalar
__device__ int   g_done;                      // cross-cluster finish counter
__device__ uint2 d_wm[TT][MOCC][NWP];         // packed (neg, nz) of w_vn; tail zero
__device__ uint2 d_gm[BB][NWP];               // packed (neg, nz) of Gamma; tail zero

// cluster barrier: arrive = .release, wait = .acquire (cluster scope)
__device__ __forceinline__ void cbar() {
    asm volatile("barrier.cluster.arrive.aligned;" ::: "memory");
    asm volatile("barrier.cluster.wait.aligned;" ::: "memory");
}

// ---------------- accurate fp32 math (flag-independent; rn division) ----
__device__ __forceinline__ float acc_expf(float x) {
    if (x < -87.0f) return 0.0f;
    if (x >  88.0f) return __int_as_float(0x7f800000);
    float kf = rintf(x * 1.4426950408889634f);
    float r  = fmaf(-kf, 0.693359375f, x);
    r = fmaf(kf, 2.12194440e-4f, r);
    float p = 1.9841270e-4f;
    p = fmaf(r, p, 1.3888889e-3f);
    p = fmaf(r, p, 8.3333333e-3f);
    p = fmaf(r, p, 4.1666667e-2f);
    p = fmaf(r, p, 1.6666667e-1f);
    p = fmaf(r, p, 0.5f);
    p = fmaf(r, p, 1.0f);
    p = fmaf(r, p, 1.0f);
    int k = (int)kf;
    float sc = __int_as_float((k + 127) << 23);
    return p * sc;
}

// log for t>0; returns EXACT +-0.0f at t==1.0f (load-bearing for phi semantics)
__device__ __forceinline__ float acc_logf(float t) {
    int ix = __float_as_int(t);
    int e  = ((ix >> 23) & 0xff) - 127;
    float m = __int_as_float((ix & 0x007fffff) | 0x3f800000);   // [1,2)
    if (m > 1.4142135f) { m *= 0.5f; e += 1; }
    float f  = m - 1.0f;
    float s  = __fdiv_rn(f, 2.0f + f);
    float s2 = s * s;
    float p  = fmaf(s2, 0.11111111f, 0.14285714f);
    p = fmaf(s2, p, 0.2f);
    p = fmaf(s2, p, 0.33333333f);
    float lm = fmaf(2.0f * s, s2 * p, 2.0f * s);
    float r  = fmaf((float)e, 0.693359375f, lm);
    r = fmaf((float)e, -2.12194440e-4f, r);
    return r;
}

// XLA / Eigen fast-tanh (f32, FMA variant) — bit-matches jnp.tanh on GPU.
__device__ __forceinline__ float xla_tanhf(float x) {
    float ax = fabsf(x);
    float xc = fminf(fmaxf(x, -7.99881172180175781f), 7.99881172180175781f);
    float x2 = xc * xc;
    float p = -2.76076847742355e-16f;
    p = fmaf(x2, p,  2.00018790482477e-13f);
    p = fmaf(x2, p, -8.60467152213735e-11f);
    p = fmaf(x2, p,  5.12229709037114e-08f);
    p = fmaf(x2, p,  1.48572235717979e-05f);
    p = fmaf(x2, p,  6.37261928875436e-04f);
    p = fmaf(x2, p,  4.89352455891786e-03f);
    float num = xc * p;
    float q = 1.19825839466702e-06f;
    q = fmaf(x2, q, 1.18534705686654e-04f);
    q = fmaf(x2, q, 2.26843463243900e-03f);
    q = fmaf(x2, q, 4.89352518554385e-03f);
    float r = __fdiv_rn(num, q);
    return (ax < 0.0004f) ? x : r;
}

// phi(x) = -log(tanh(x/2)) with the reference's exact tanh quantization.
__device__ __forceinline__ float phi_f(float x) {
    return -acc_logf(xla_tanhf(0.5f * x));
}

// |sin(argf)| accurate to ~1e-12: dd-pi reduction + odd Taylor to r^15.
__device__ __forceinline__ float abs_sin_acc(float argf) {
    double a = (double)argf;
    double k = rint(a * 0.31830988618379067154);
    double r = fma(-k, 3.141592653589793116, a);
    r = fma(-k, 1.2246467991473531772e-16, r);
    double r2 = r * r;
    double p = -7.6471637318198164759e-13;
    p = fma(r2, p,  1.6059043836821614599e-10);
    p = fma(r2, p, -2.5052108385441718775e-08);
    p = fma(r2, p,  2.7557319223985890653e-06);
    p = fma(r2, p, -1.9841269841269841253e-04);
    p = fma(r2, p,  8.3333333333333332177e-03);
    p = fma(r2, p, -1.6666666666666666574e-01);
    p = fma(r2, p,  1.0);
    return fabsf((float)(r * p));
}

// ---------------- wide scan kernel: H masks + packed w_vn masks ---------
__global__ void k_scan(const float* __restrict__ H, const float* __restrict__ w_vn) {
    int t = blockIdx.x * 256 + threadIdx.x;
    const float* base;
    int c;
    bool isH = (t < HW_WORDS);
    if (isH) {
        int m = t / NW; c = t % NW;
        base = H + (size_t)m * TN + c * 32;
    } else {
        int u = t - HW_WORDS;
        int row = u / NW; c = u % NW;
        base = w_vn + (size_t)row * TN + c * 32;
    }
    int nvec = (c == NW - 1) ? 1 : 8;                 // last word: only 4 floats
    unsigned neg = 0, nz = 0;
    for (int v = 0; v < nvec; v++) {
        float4 f = reinterpret_cast<const float4*>(base)[v];
        int k = v * 4;
        neg |= ((f.x < 0.0f) ? 1u : 0u) << k;
        neg |= ((f.y < 0.0f) ? 1u : 0u) << (k + 1);
        neg |= ((f.z < 0.0f) ? 1u : 0u) << (k + 2);
        neg |= ((f.w < 0.0f) ? 1u : 0u) << (k + 3);
        nz  |= ((f.x != 0.0f) ? 1u : 0u) << k;
        nz  |= ((f.y != 0.0f) ? 1u : 0u) << (k + 1);
        nz  |= ((f.z != 0.0f) ? 1u : 0u) << (k + 2);
        nz  |= ((f.w != 0.0f) ? 1u : 0u) << (k + 3);
    }
    if (isH) {
        (&d_hmask[0][0])[t] = nz;
    } else {
        int u = t - HW_WORDS;
        int row = u / NW;
        (&d_wm[0][0][0])[(size_t)row * NWP + c] = make_uint2(neg, nz);
    }
}

// ---------------- k_rows: parallel mask loads + warp prefix-scan ---------
__global__ void k_rows(const float* __restrict__ ex, const float* __restrict__ ez) {
    int gw = (blockIdx.x * blockDim.x + threadIdx.x) >> 5;
    int lane = threadIdx.x & 31;
    if (gw >= MOCC) return;
    int m = gw;

    unsigned w0 = d_hmask[m][lane];
    unsigned w1 = (lane < NW - 32) ? d_hmask[m][lane + 32] : 0u;
    int p0 = __popc(w0), p1 = __popc(w1);
    int s0 = p0;
    #pragma unroll
    for (int o = 1; o < 32; o <<= 1) { int v = __shfl_up_sync(0xffffffffu, s0, o); if (lane >= o) s0 += v; }
    int total0 = __shfl_sync(0xffffffffu, s0, 31);
    int s1 = p1;
    #pragma unroll
    for (int o = 1; o < 32; o <<= 1) { int v = __shfl_up_sync(0xffffffffu, s1, o); if (lane >= o) s1 += v; }
    int deg = total0 + __shfl_sync(0xffffffffu, s1, 31);
    int b0 = s0 - p0;
    int b1 = total0 + s1 - p1;
    unsigned x = w0; int idx = 0;
    while (x) { int bit = __ffs(x) - 1; x &= x - 1;
                int pos = b0 + idx++; if (pos < MAXD) d_row_cols[m][pos] = lane * 32 + bit; }
    x = w1; idx = 0;
    while (x) { int bit = __ffs(x) - 1; x &= x - 1;
                int pos = b1 + idx++; if (pos < MAXD) d_row_cols[m][pos] = (lane + 32) * 32 + bit; }
    if (deg > MAXD) deg = MAXD;
    if (lane == 0) d_row_deg[m] = deg;
    for (int b = 0; b < BB; b++) d_C[b][m][lane] = 0.0f;
    __syncwarp();

    bool act = (lane < deg);
    int col = act ? d_row_cols[m][lane] : 0;
    if (act) {
        int pos = atomicAdd(&d_col_cnt[col], 1);
        if (pos < CMAXD) d_col_edges[col][pos] = m * MAXD + lane;
    }
    float ev[BB];
    #pragma unroll
    for (int b = 0; b < BB; b++)
        ev[b] = act ? ((col < NN) ? ex[b * NN + col] : ez[b * NN + (col - NN)]) : 0.0f;
    #pragma unroll
    for (int b = 0; b < BB; b++) {
        unsigned bal = __ballot_sync(0xffffffffu, act && (ev[b] != 0.0f));
        if (lane == 0) d_synsign[b][m] = (__popc(bal) & 1) ? -1.0f : 1.0f;
    }
}

// ---------------- k_wprep: wedge gather + column sort/pad/reset ----------
__global__ void k_wprep(const float* __restrict__ w_vn) {
    if (blockIdx.x < GATH_BLOCKS) {
        int t = blockIdx.x * 256 + threadIdx.x;
        int slot = t & (MAXD - 1);
        int m    = (t >> 5) & (MOCC - 1);
        int it   = t >> 15;
        float w = 0.0f;
        if (slot < d_row_deg[m]) {
            int col = d_row_cols[m][slot];
            w = w_vn[((size_t)it * MOCC + m) * TN + col];
        }
        d_wedge[it][m][slot] = w;
    } else {
        int j = (blockIdx.x - GATH_BLOCKS) * 256 + threadIdx.x;
        if (j >= TN) return;
        int cnt = d_col_cnt[j];
        if (cnt > CMAXD) cnt = CMAXD;
        int e[CMAXD];
        for (int k = 0; k < cnt; k++) e[k] = d_col_edges[j][k];
        for (int i = 1; i < cnt; i++) {               // ascending m order
            int key = e[i], p = i - 1;
            while (p >= 0 && e[p] > key) { e[p + 1] = e[p]; p--; }
            e[p + 1] = key;
        }
        for (int k = 0; k < cnt; k++) d_col_edges[j][k] = e[k];
        for (int k = cnt; k < PADCD; k++) d_col_edges[j][k] = DUMMY_EDGE;
        d_col_deg[j] = cnt;
        d_col_cnt[j] = 0;                             // reset for next replay
    }
}

// ---------------- CN row update, full-warp fallback (deg>16 rows) --------
__device__ __forceinline__ void cn_solo(int b, int m, int it, float gconst,
                                        int lane, const float* __restrict__ w_cn) {
    const uint2* wm = d_wm[it][m];
    int cnt = 0;
    if (it == 0) {
        unsigned GN = (gconst < 0.0f) ? 0xffffffffu : 0u;
        unsigned GZ = (gconst != 0.0f) ? 0xffffffffu : 0u;
        #pragma unroll
        for (int q = 0; q < 2; q++) {
            uint2 w = wm[lane + 32 * q];
            cnt += __popc((GN ^ w.x) & GZ & w.y);
        }
    } else {
        #pragma unroll
        for (int q = 0; q < 2; q++) {
            uint2 w = wm[lane + 32 * q];
            uint2 g = d_gm[b][lane + 32 * q];
            cnt += __popc((g.x ^ w.x) & g.y & w.y);
        }
    }
    for (int o = 16; o; o >>= 1) cnt += __shfl_xor_sync(0xffffffffu, cnt, o);
    int parity = cnt & 1;

    int deg = d_row_deg[m];
    bool act = (lane < deg);
    float V = 0.0f, phi = 0.0f;
    int corr = 0;
    if (act) {
        int j = d_row_cols[m][lane];
        float G = (it == 0) ? gconst : d_Gamma[b][j];
        float Cold = d_C[b][m][lane];
        float w = d_wedge[it][m][lane];
        float x = G - Cold;
        x = fminf(fmaxf(x, -30.0f), 30.0f);
        V = x * w;
        int pneg = (((G < 0.0f) != (w < 0.0f)) && (G != 0.0f) && (w != 0.0f)) ? 1 : 0;
        int vneg = (V < 0.0f) ? 1 : 0;
        corr = pneg ^ vneg;
        if (V != 0.0f) phi = phi_f(fabsf(V));
    }
    unsigned cb = __ballot_sync(0xffffffffu, corr);
    parity ^= (__popc(cb) & 1);

    float A = phi;
    for (int o = 16; o; o >>= 1) A += __shfl_xor_sync(0xffffffffu, A, o);

    if (act) {
        float P = parity ? -1.0f : 1.0f;
        float first = (V < 0.0f) ? -P : P;
        float s2 = A - phi;
        float second = (s2 != 0.0f) ? phi_f(s2) : 0.0f;
        d_C[b][m][lane] = ((first * second) * d_synsign[b][m]) * w_cn[it * MOCC + m];
    }
}

// ---------------- k_bp: 8-CTA clusters, fully staged 2-task CN ----------
__global__ void __launch_bounds__(BPTHR, 1) __cluster_dims__(CLSZ, 1, 1)
k_bp(const float* __restrict__ ex, const float* __restrict__ ez,
     const float* __restrict__ ep,
     const float* __restrict__ Gx, const float* __restrict__ Gz,
     const float* __restrict__ w_llr, const float* __restrict__ w_cn,
     float* __restrict__ out)
{
    const int tid  = threadIdx.x;
    const int lane = tid & 31;
    const int b    = blockIdx.x / CLSZ;               // batch for this cluster
    const int rank = blockIdx.x % CLSZ;               // cta rank in cluster
    const int cw   = rank * (BPTHR / 32) + (tid >> 5);  // cluster warp id 0..255
    const int half = lane >> 4;
    const int hl   = lane & 15;

    // ---- prologue: cache static per-warp state in registers ----
    int  cn_m[2], cn_j[2];
    bool cn_act[2], cn_packed[2];
    float cn_syn[2], Creg[2];
    #pragma unroll
    for (int s = 0; s < 2; s++) {
        int t = cw + s * 256;
        int m1 = 2 * t, m2 = 2 * t + 1;
        int deg1 = d_row_deg[m1], deg2 = d_row_deg[m2];
        cn_packed[s] = (deg1 <= 16 && deg2 <= 16);
        int m   = half ? m2 : m1;
        int deg = half ? deg2 : deg1;
        cn_m[s]   = m;
        cn_act[s] = (hl < deg);
        cn_j[s]   = cn_act[s] ? d_row_cols[m][hl] : 0;
        cn_syn[s] = d_synsign[b][m];
        Creg[s]   = 0.0f;
    }
    // VN task
    int vj = cw * 32 + lane;
    bool vin = (cw < NW) && (vj < TN);
    int  ve[PADCD];
    int  vcd = 0;
    bool vmask = false;
    if (vin) {
        vcd = d_col_deg[vj];
        #pragma unroll
        for (int k = 0; k < PADCD; k++) ve[k] = d_col_edges[vj][k];
        float mk = (vj < NN) ? ex[b * NN + vj] : ez[b * NN + (vj - NN)];
        vmask = (mk == 1.0f);
    } else {
        #pragma unroll
        for (int k = 0; k < PADCD; k++) ve[k] = DUMMY_EDGE;
    }

    float e0  = ep[0];
    float llr = acc_logf(__fdiv_rn(1.0f - e0, e0));
    float gconst = llr * w_llr[0];

    for (int it = 0; it < TT; it++) {
        bool both_packed = cn_packed[0] && cn_packed[1];
        if (both_packed) {
            // ---- stage A: all loads (gm shared across tasks) ----
            uint2 gm[4];
            if (it != 0) {
                #pragma unroll
                for (int q = 0; q < 4; q++) gm[q] = d_gm[b][hl + 16 * q];
            }
            float wreg[2], wcnreg[2], Greg[2];
            uint2 wm[2][4];
            #pragma unroll
            for (int s = 0; s < 2; s++) {
                int m = cn_m[s];
                wreg[s]   = cn_act[s] ? d_wedge[it][m][hl] : 0.0f;
                wcnreg[s] = w_cn[it * MOCC + m];
                Greg[s]   = (it == 0) ? gconst : (cn_act[s] ? d_Gamma[b][cn_j[s]] : 0.0f);
                #pragma unroll
                for (int q = 0; q < 4; q++) wm[s][q] = d_wm[it][m][hl + 16 * q];
            }
            // ---- stage B: popc (4 unconditional words/task) ----
            int cnt[2];
            #pragma unroll
            for (int s = 0; s < 2; s++) {
                int c0 = 0;
                if (it == 0) {
                    unsigned GN = (gconst < 0.0f) ? 0xffffffffu : 0u;
                    unsigned GZ = (gconst != 0.0f) ? 0xffffffffu : 0u;
                    #pragma unroll
                    for (int q = 0; q < 4; q++)
                        c0 += __popc((GN ^ wm[s][q].x) & GZ & wm[s][q].y);
                } else {
                    #pragma unroll
                    for (int q = 0; q < 4; q++)
                        c0 += __popc((gm[q].x ^ wm[s][q].x) & gm[q].y & wm[s][q].y);
                }
                cnt[s] = c0;
            }
            // ---- stage C: V, corr, first phi (both chains adjacent) ----
            float V[2], ph[2];
            int corr[2];
            #pragma unroll
            for (int s = 0; s < 2; s++) {
                V[s] = 0.0f; ph[s] = 0.0f; corr[s] = 0;
                if (cn_act[s]) {
                    float G = Greg[s];
                    float x = G - Creg[s];
                    x = fminf(fmaxf(x, -30.0f), 30.0f);
                    V[s] = x * wreg[s];
                    int pneg = (((G < 0.0f) != (wreg[s] < 0.0f)) && (G != 0.0f) && (wreg[s] != 0.0f)) ? 1 : 0;
                    int vneg = (V[s] < 0.0f) ? 1 : 0;
                    corr[s] = pneg ^ vneg;
                }
            }
            #pragma unroll
            for (int s = 0; s < 2; s++)
                if (cn_act[s] && V[s] != 0.0f) ph[s] = phi_f(fabsf(V[s]));
            // ---- stage D: reductions (both tasks) ----
            int par[2];
            #pragma unroll
            for (int s = 0; s < 2; s++) {
                int c0 = cnt[s];
                for (int o = 8; o; o >>= 1) c0 += __shfl_xor_sync(0xffffffffu, c0, o);
                par[s] = c0 & 1;
            }
            unsigned cb0 = __ballot_sync(0xffffffffu, corr[0]);
            unsigned cb1 = __ballot_sync(0xffffffffu, corr[1]);
            par[0] ^= (__popc(half ? (cb0 >> 16) : (cb0 & 0xFFFFu)) & 1);
            par[1] ^= (__popc(half ? (cb1 >> 16) : (cb1 & 0xFFFFu)) & 1);
            float A[2];
            #pragma unroll
            for (int s = 0; s < 2; s++) {
                float a = ph[s];
                for (int o = 8; o; o >>= 1) a += __shfl_xor_sync(0xffffffffu, a, o);
                A[s] = a;
            }
            // ---- stage E: second phi (both chains adjacent) + stores ----
            float sec[2];
            #pragma unroll
            for (int s = 0; s < 2; s++) {
                float s2 = A[s] - ph[s];
                sec[s] = (cn_act[s] && s2 != 0.0f) ? phi_f(s2) : 0.0f;
            }
            #pragma unroll
            for (int s = 0; s < 2; s++) {
                if (cn_act[s]) {
                    float P = par[s] ? -1.0f : 1.0f;
                    float first = (V[s] < 0.0f) ? -P : P;
                    float outv = ((first * sec[s]) * cn_syn[s]) * wcnreg[s];
                    Creg[s] = outv;
                    d_C[b][cn_m[s]][hl] = outv;
                }
            }
        } else {
            #pragma unroll
            for (int s = 0; s < 2; s++) {
                int t = cw + s * 256;
                cn_solo(b, 2 * t,     it, gconst, lane, w_cn);
                cn_solo(b, 2 * t + 1, it, gconst, lane, w_cn);
            }
        }
        cbar();

        // ---- VN phase (1 task/warp) + loss terms for it-1 ----
        float wl = w_llr[it + 1];
        if (cw < NW) {
            float g = 0.0f;
            if (vin) {
                const float* Cb = &d_C[b][0][0];
                float sum = 0.0f;
                #pragma unroll
                for (int k = 0; k < PADCD; k++) sum += Cb[ve[k]];
                if (vcd > PADCD)
                    for (int k = PADCD; k < vcd; k++) sum += Cb[d_col_edges[vj][k]];
                g = llr * wl + sum;
                d_Gamma[b][vj] = g;
                float pmv = 0.0f;
                if (vmask) pmv = __fdiv_rn(1.0f, 1.0f + acc_expf(g));
                d_pm2[it & 1][b][vj] = pmv;
            }
            unsigned bneg = __ballot_sync(0xffffffffu, vin && (g < 0.0f));
            unsigned bnz  = __ballot_sync(0xffffffffu, vin && (g != 0.0f));
            if (lane == 0) d_gm[b][cw] = make_uint2(bneg, bnz);
        } else if (it > 0 && cw < NW + LT2) {
            int k2 = cw - NW;
            int buf = (it - 1) & 1;
            const float* Grow  = (k2 < KK) ? Gx + (size_t)k2 * NN : Gz + (size_t)(k2 - KK) * NN;
            const float* pmrow = (k2 < KK) ? &d_pm2[buf][b][0] : &d_pm2[buf][b][NN];
            float s = 0.0f;
            for (int n = lane; n < NN; n += 32) s += pmrow[n] * Grow[n];
            for (int o = 16; o; o >>= 1) s += __shfl_xor_sync(0xffffffffu, s, o);
            if (lane == 0) d_lossterm2[b][it - 1][k2] = abs_sin_acc(1.5707964f * s);
        }
        cbar();
    }

    // ---- epilogue: loss terms for it = TT-1 (pm buffer (TT-1)&1) ----
    if (cw < LT2) {
        int k2 = cw;
        int buf = (TT - 1) & 1;
        const float* Grow  = (k2 < KK) ? Gx + (size_t)k2 * NN : Gz + (size_t)(k2 - KK) * NN;
        const float* pmrow = (k2 < KK) ? &d_pm2[buf][b][0] : &d_pm2[buf][b][NN];
        float s = 0.0f;
        for (int n = lane; n < NN; n += 32) s += pmrow[n] * Grow[n];
        for (int o = 16; o; o >>= 1) s += __shfl_xor_sync(0xffffffffu, s, o);
        if (lane == 0) d_lossterm2[b][TT - 1][k2] = abs_sin_acc(1.5707964f * s);
    }
    cbar();

    // ---- per-batch reduction + cross-cluster finish ----
    if (rank == 0 && tid == 0) {
        float v[TT];
        for (int i = 0; i < TT; i++) {
            float tsum = 0.0f;
            for (int k = 0; k < LT2; k++) tsum += d_lossterm2[b][i][k];
            v[i] = tsum;
        }
        float best = v[0]; int bi = 0;
        for (int i = 1; i < TT; i++) if (v[i] < best) { best = v[i]; bi = i; }
        float cs = 0.0f;
        for (int i = 0; i <= bi; i++) cs += v[i];
        d_lossb[b] = __fdiv_rn(cs, (float)(bi + 1));
        __threadfence();
        int prev = atomicAdd(&g_done, 1);
        if (prev == BB - 1) {                         // last cluster finishes
            __threadfence();
            float tot = 0.0f;
            for (int bb = 0; bb < BB; bb++) tot += d_lossb[bb];
            out[0] = tot * 0.125f;
            g_done = 0;                               // reset for next replay
            __threadfence();
        }
    }
}

// ---------------- launch ----------------
extern "C" void kernel_launch(void* const* d_in, const int* in_sizes, int n_in,
                              void* d_out, int out_size) {
    const float* ex    = (const float*)d_in[0];
    const float* ez    = (const float*)d_in[1];
    const float* ep    = (const float*)d_in[2];
    const float* H     = (const float*)d_in[3];
    const float* Gx    = (const float*)d_in[6];
    const float* Gz    = (const float*)d_in[7];
    const float* w_vn  = (const float*)d_in[8];
    const float* w_llr = (const float*)d_in[9];
    const float* w_cn  = (const float*)d_in[10];
    float* out = (float*)d_out;

    k_scan <<<SCAN_WORDS / 256, 256>>>(H, w_vn);
    k_rows <<<MOCC / 8, 256>>>(ex, ez);
    k_wprep<<<GATH_BLOCKS + SORT_BLOCKS, 256>>>(w_vn);
    k_bp   <<<BB * CLSZ, BPTHR>>>(ex, ez, ep, Gx, Gz, w_llr, w_cn, out);
}